// round 1
// baseline (speedup 1.0000x reference)
#include <cuda_runtime.h>

#define H 4096
#define NUM_LAYERS 8
#define WARPS_PER_BLOCK 8
#define THREADS (WARPS_PER_BLOCK * 32)
#define ROWS_PER_BLOCK WARPS_PER_BLOCK

// Ping-pong hidden-state buffers (allocation-free scratch).
__device__ float g_h[2][H];

// GEMV: out[row] = act( dot(W[row, :], h_in) + b0[row] + b1[row] )
// W is row-major [H, H]; one warp per output row; h_in staged in smem.
template <bool TANH, bool HAS_B1>
__global__ void __launch_bounds__(THREADS)
gemv_kernel(const float* __restrict__ W,
            const float* __restrict__ b0,
            const float* __restrict__ b1,
            const float* __restrict__ h_in,
            float* __restrict__ h_out) {
    __shared__ float sh[H];

    // Cooperative load of the input vector (16 KB) into shared memory.
    const float4* hv_g = reinterpret_cast<const float4*>(h_in);
    float4* sh4 = reinterpret_cast<float4*>(sh);
    #pragma unroll
    for (int i = threadIdx.x; i < H / 4; i += THREADS)
        sh4[i] = hv_g[i];
    __syncthreads();

    const int warp = threadIdx.x >> 5;
    const int lane = threadIdx.x & 31;
    const int row  = blockIdx.x * ROWS_PER_BLOCK + warp;

    const float4* Wr = reinterpret_cast<const float4*>(W + (size_t)row * H);

    // 4096 floats / row = 1024 float4 = 32 float4 per lane.
    // Two accumulators to break the FFMA dependence chain a bit.
    float acc0 = 0.f, acc1 = 0.f;
    #pragma unroll
    for (int i = 0; i < H / 4 / 32; i += 2) {
        float4 w0 = Wr[lane + (i + 0) * 32];
        float4 x0 = sh4[lane + (i + 0) * 32];
        float4 w1 = Wr[lane + (i + 1) * 32];
        float4 x1 = sh4[lane + (i + 1) * 32];
        acc0 += w0.x * x0.x + w0.y * x0.y + w0.z * x0.z + w0.w * x0.w;
        acc1 += w1.x * x1.x + w1.y * x1.y + w1.z * x1.z + w1.w * x1.w;
    }
    float acc = acc0 + acc1;

    #pragma unroll
    for (int off = 16; off; off >>= 1)
        acc += __shfl_down_sync(0xffffffffu, acc, off);

    if (lane == 0) {
        float v = acc + b0[row];
        if (HAS_B1) v += b1[row];
        h_out[row] = TANH ? tanhf(v) : v;
    }
}

extern "C" void kernel_launch(void* const* d_in, const int* in_sizes, int n_in,
                              void* d_out, int out_size) {
    const float* x    = (const float*)d_in[0];  // [1, H]
    const float* Wxh  = (const float*)d_in[1];  // [L, H, H]
    const float* bxh  = (const float*)d_in[2];  // [L, H]
    // d_in[3] = Whh — multiplied by a zero vector in the reference; never read.
    const float* bhh  = (const float*)d_in[4];  // [L, H]
    const float* fc_w = (const float*)d_in[5];  // [H, H]
    const float* fc_b = (const float*)d_in[6];  // [H]
    float* out = (float*)d_out;

    float* hbuf = nullptr;
    cudaGetSymbolAddress((void**)&hbuf, g_h);
    float* h0 = hbuf;      // g_h[0]
    float* h1 = hbuf + H;  // g_h[1]

    const dim3 grid(H / ROWS_PER_BLOCK);  // 512 blocks
    const dim3 block(THREADS);            // 256 threads

    const float* cur = x;
    float* nxt = h0;
    for (int i = 0; i < NUM_LAYERS; i++) {
        gemv_kernel<true, true><<<grid, block>>>(
            Wxh + (size_t)i * H * H, bxh + (size_t)i * H, bhh + (size_t)i * H,
            cur, nxt);
        cur = nxt;
        nxt = (nxt == h0) ? h1 : h0;
    }
    // Final linear layer: no tanh, single bias.
    gemv_kernel<false, false><<<grid, block>>>(fc_w, fc_b, nullptr, cur, out);
}